// round 8
// baseline (speedup 1.0000x reference)
#include <cuda_runtime.h>
#include <cuda_bf16.h>
#include <cstdint>

#define SEQ 1024
#define DH  64
#define NBH 64
#define MT  128
#define NC  128

#define S1  144
#define S2  272

// smem layout (bytes)
#define P_QH   0
#define P_QL   18432
#define P_KH   36864
#define P_KL   55296
#define P_KRAW 73728      // 32 KB raw fp32 K chunk (cp.async staging)
#define P_VH   106496
#define P_VL   123904
#define P_WH   141312
#define P_WL   176128
#define ST_SUM 141312     // reused (WH region) between passes
#define ST_INV 210944
#define SMEM_TOTAL 211456

__device__ __forceinline__ uint32_t sm_u32(const void* p) {
    uint32_t a;
    asm("{ .reg .u64 t; cvta.to.shared.u64 t, %1; cvt.u32.u64 %0, t; }" : "=r"(a) : "l"(p));
    return a;
}
__device__ __forceinline__ uint32_t pack2(__nv_bfloat16 a, __nv_bfloat16 b) {
    return (uint32_t)__bfloat16_as_ushort(a) | ((uint32_t)__bfloat16_as_ushort(b) << 16);
}
__device__ __forceinline__ void split4(float4 v, uint2& h, uint2& l) {
    __nv_bfloat16 h0 = __float2bfloat16(v.x), h1 = __float2bfloat16(v.y);
    __nv_bfloat16 h2 = __float2bfloat16(v.z), h3 = __float2bfloat16(v.w);
    __nv_bfloat16 l0 = __float2bfloat16(v.x - __bfloat162float(h0));
    __nv_bfloat16 l1 = __float2bfloat16(v.y - __bfloat162float(h1));
    __nv_bfloat16 l2 = __float2bfloat16(v.z - __bfloat162float(h2));
    __nv_bfloat16 l3 = __float2bfloat16(v.w - __bfloat162float(h3));
    h.x = pack2(h0, h1); h.y = pack2(h2, h3);
    l.x = pack2(l0, l1); l.y = pack2(l2, l3);
}

#define LDSM4(a, addr) \
    asm volatile("ldmatrix.sync.aligned.m8n8.x4.shared.b16 {%0,%1,%2,%3}, [%4];" \
        : "=r"((a)[0]), "=r"((a)[1]), "=r"((a)[2]), "=r"((a)[3]) : "r"(addr))

#define CPASYNC16(dst, src) \
    asm volatile("cp.async.cg.shared.global [%0], [%1], 16;" :: "r"(dst), "l"(src))
#define CPCOMMIT() asm volatile("cp.async.commit_group;" ::: "memory")
#define CPWAIT0()  asm volatile("cp.async.wait_group 0;" ::: "memory")

__device__ __forceinline__ void mma_bf16(float* c, const uint32_t* a, uint32_t b0, uint32_t b1) {
    asm volatile("mma.sync.aligned.m16n8k16.row.col.f32.bf16.bf16.f32 "
        "{%0,%1,%2,%3}, {%4,%5,%6,%7}, {%8,%9}, {%0,%1,%2,%3};"
        : "+f"(c[0]), "+f"(c[1]), "+f"(c[2]), "+f"(c[3])
        : "r"(a[0]), "r"(a[1]), "r"(a[2]), "r"(a[3]), "r"(b0), "r"(b1));
}

__global__ __launch_bounds__(512, 1)
void attn_fused(const float* __restrict__ Qg, const float* __restrict__ Kg,
                const float* __restrict__ Vg, const float* __restrict__ bias,
                float* __restrict__ outO, float* __restrict__ outW)
{
    extern __shared__ char sm[];
    const uint32_t sb = sm_u32(sm);
    const int tid = threadIdx.x;
    const int lane = tid & 31, wid = tid >> 5;
    const int gid = lane >> 2, tig = lane & 3;
    const int wm = wid >> 2, wn = wid & 3;
    const int bh = blockIdx.y, qb = blockIdx.x * MT;

    const float* Kbase = Kg + (size_t)bh * SEQ * DH;

    // prefetch raw K chunk 0 (overlaps Q conversion)
    {
        const float* src = Kbase + tid * 16;
        uint32_t dst = sb + P_KRAW + tid * 64;
        #pragma unroll
        for (int j = 0; j < 4; ++j) CPASYNC16(dst + j * 16, src + j * 4);
        CPCOMMIT();
    }

    // ---- Q tile: pre-scale + split ----
    {
        const float* Qp = Qg + ((size_t)bh * SEQ + qb) * DH;
        int r = tid >> 2, c0 = (tid & 3) * 16;
        #pragma unroll
        for (int j = 0; j < 4; ++j) {
            float4 v = *(const float4*)(Qp + r * DH + c0 + j * 4);
            v.x *= 0.125f; v.y *= 0.125f; v.z *= 0.125f; v.w *= 0.125f;
            uint2 h, l; split4(v, h, l);
            *(uint2*)(sm + P_QH + r * S1 + (c0 + j * 4) * 2) = h;
            *(uint2*)(sm + P_QL + r * S1 + (c0 + j * 4) * 2) = l;
        }
    }
    __syncthreads();

    // ---- preload Q fragments (reused by BOTH passes) ----
    uint32_t aqh[4][2][4], aql[4][2][4];
    #pragma unroll
    for (int kt = 0; kt < 4; ++kt)
        #pragma unroll
        for (int mi = 0; mi < 2; ++mi) {
            uint32_t ra = sb + P_QH + (uint32_t)((wm * 32 + mi * 16 + (lane & 15)) * S1
                         + (lane >> 4) * 16 + kt * 32);
            LDSM4(aqh[kt][mi], ra);
            LDSM4(aql[kt][mi], ra + (P_QL - P_QH));
        }

    // converts KRAW (fp32) -> split KH/KL
    auto convK = [&]() {
        int r = tid >> 2, c0 = (tid & 3) * 16;
        #pragma unroll
        for (int j = 0; j < 4; ++j) {
            float4 v = *(const float4*)(sm + P_KRAW + r * 256 + (c0 + j * 4) * 4);
            uint2 h, l; split4(v, h, l);
            *(uint2*)(sm + P_KH + r * S1 + (c0 + j * 4) * 2) = h;
            *(uint2*)(sm + P_KL + r * S1 + (c0 + j * 4) * 2) = l;
        }
    };
    auto prefetchK = [&](int nc) {
        const float* src = Kbase + (size_t)nc * NC * DH + tid * 16;
        uint32_t dst = sb + P_KRAW + tid * 64;
        #pragma unroll
        for (int j = 0; j < 4; ++j) CPASYNC16(dst + j * 16, src + j * 4);
        CPCOMMIT();
    };
    auto qkmma = [&](float acc[2][4][4]) {
        #pragma unroll
        for (int mi = 0; mi < 2; ++mi)
            #pragma unroll
            for (int ni = 0; ni < 4; ++ni)
                #pragma unroll
                for (int e = 0; e < 4; ++e) acc[mi][ni][e] = 0.f;
        #pragma unroll
        for (int kt = 0; kt < 4; ++kt) {
            uint32_t bh4[2][4], bl4[2][4];
            #pragma unroll
            for (int p = 0; p < 2; ++p) {
                uint32_t addr = sb + P_KH + (uint32_t)((wn * 32 + p * 16 + (lane & 15)) * S1
                               + (lane >> 4) * 16 + kt * 32);
                LDSM4(bh4[p], addr);
                LDSM4(bl4[p], addr + (P_KL - P_KH));
            }
            #pragma unroll
            for (int p = 0; p < 2; ++p)
                #pragma unroll
                for (int q = 0; q < 2; ++q) {
                    uint32_t b0h = bh4[p][q], b1h = bh4[p][q + 2];
                    uint32_t b0l = bl4[p][q], b1l = bl4[p][q + 2];
                    #pragma unroll
                    for (int mi = 0; mi < 2; ++mi) {
                        float* c = acc[mi][p * 2 + q];
                        mma_bf16(c, aqh[kt][mi], b0h, b1h);
                        mma_bf16(c, aqh[kt][mi], b0l, b1l);
                        mma_bf16(c, aql[kt][mi], b0h, b1h);
                    }
                }
        }
    };

    // ================= pass A: row sums of exp(scores) =================
    float rs[2][2] = {{0.f, 0.f}, {0.f, 0.f}};
    for (int nc = 0; nc < 8; ++nc) {
        CPWAIT0();
        __syncthreads();
        convK();
        __syncthreads();
        if (nc < 7) prefetchK(nc + 1);
        float acc[2][4][4];
        qkmma(acc);
        #pragma unroll
        for (int mi = 0; mi < 2; ++mi) {
            int r0 = qb + wm * 32 + mi * 16 + gid;
            #pragma unroll
            for (int ni = 0; ni < 4; ++ni) {
                int c = nc * NC + wn * 32 + ni * 8 + tig * 2;
                float2 b0 = *(const float2*)(bias + (size_t)r0 * SEQ + c);
                rs[mi][0] += __expf(acc[mi][ni][0] + b0.x) + __expf(acc[mi][ni][1] + b0.y);
                float2 b1 = *(const float2*)(bias + (size_t)(r0 + 8) * SEQ + c);
                rs[mi][1] += __expf(acc[mi][ni][2] + b1.x) + __expf(acc[mi][ni][3] + b1.y);
            }
        }
    }

    // ---- reduce -> 1/rowsum ----
    {
        float* st = (float*)(sm + ST_SUM);
        int slot = wn * 4 + tig;
        #pragma unroll
        for (int mi = 0; mi < 2; ++mi)
            #pragma unroll
            for (int h = 0; h < 2; ++h)
                st[(wm * 32 + mi * 16 + h * 8 + gid) * 16 + slot] = rs[mi][h];
    }
    __syncthreads();
    if (tid < 128) {
        float* st = (float*)(sm + ST_SUM);
        float s = 0.f;
        #pragma unroll
        for (int i = 0; i < 16; ++i) s += st[tid * 16 + i];
        ((float*)(sm + ST_INV))[tid] = 1.f / s;
    }
    __syncthreads();

    float inv[2][2];
    #pragma unroll
    for (int mi = 0; mi < 2; ++mi)
        #pragma unroll
        for (int h = 0; h < 2; ++h)
            inv[mi][h] = ((const float*)(sm + ST_INV))[wm * 32 + mi * 16 + h * 8 + gid];

    prefetchK(0);

    // ================= pass B: W = exp*inv -> gmem+smem, O = W@V =================
    float accO[2][2][4];
    #pragma unroll
    for (int mi = 0; mi < 2; ++mi)
        #pragma unroll
        for (int ni = 0; ni < 2; ++ni)
            #pragma unroll
            for (int e = 0; e < 4; ++e) accO[mi][ni][e] = 0.f;

    for (int nc = 0; nc < 8; ++nc) {
        CPWAIT0();
        __syncthreads();          // KRAW ready; prev PV MMA done (frees W/V smem)
        convK();
        __syncthreads();
        if (nc < 7) prefetchK(nc + 1);
        float acc[2][4][4];
        qkmma(acc);

        // epilogue: W = exp(acc+bias)*inv -> gmem + split smem
        #pragma unroll
        for (int mi = 0; mi < 2; ++mi) {
            int r0 = qb + wm * 32 + mi * 16 + gid;
            #pragma unroll
            for (int ni = 0; ni < 4; ++ni) {
                int cl = wn * 32 + ni * 8 + tig * 2;
                int c = nc * NC + cl;
                float2 b0 = *(const float2*)(bias + (size_t)r0 * SEQ + c);
                float w0 = __expf(acc[mi][ni][0] + b0.x) * inv[mi][0];
                float w1 = __expf(acc[mi][ni][1] + b0.y) * inv[mi][0];
                *(float2*)(outW + ((size_t)bh * SEQ + r0) * SEQ + c) = make_float2(w0, w1);
                float2 b1 = *(const float2*)(bias + (size_t)(r0 + 8) * SEQ + c);
                float w2 = __expf(acc[mi][ni][2] + b1.x) * inv[mi][1];
                float w3 = __expf(acc[mi][ni][3] + b1.y) * inv[mi][1];
                *(float2*)(outW + ((size_t)bh * SEQ + r0 + 8) * SEQ + c) = make_float2(w2, w3);
                // split to smem (rows local)
                int rl0 = wm * 32 + mi * 16 + gid;
                __nv_bfloat16 h0 = __float2bfloat16(w0), h1 = __float2bfloat16(w1);
                __nv_bfloat16 l0 = __float2bfloat16(w0 - __bfloat162float(h0));
                __nv_bfloat16 l1 = __float2bfloat16(w1 - __bfloat162float(h1));
                *(uint32_t*)(sm + P_WH + rl0 * S2 + cl * 2) = pack2(h0, h1);
                *(uint32_t*)(sm + P_WL + rl0 * S2 + cl * 2) = pack2(l0, l1);
                __nv_bfloat16 h2 = __float2bfloat16(w2), h3 = __float2bfloat16(w3);
                __nv_bfloat16 l2 = __float2bfloat16(w2 - __bfloat162float(h2));
                __nv_bfloat16 l3 = __float2bfloat16(w3 - __bfloat162float(h3));
                *(uint32_t*)(sm + P_WH + (rl0 + 8) * S2 + cl * 2) = pack2(h2, h3);
                *(uint32_t*)(sm + P_WL + (rl0 + 8) * S2 + cl * 2) = pack2(l2, l3);
            }
        }
        // V chunk -> transposed split smem [d][s]
        {
            int s0 = (tid & 63) * 2, d0 = (tid >> 6) * 8;
            const float* vp = Vg + ((size_t)bh * SEQ + nc * NC + s0) * DH + d0;
            float va[8], vb[8];
            *(float4*)(va)     = *(const float4*)(vp);
            *(float4*)(va + 4) = *(const float4*)(vp + 4);
            *(float4*)(vb)     = *(const float4*)(vp + DH);
            *(float4*)(vb + 4) = *(const float4*)(vp + DH + 4);
            #pragma unroll
            for (int d = 0; d < 8; ++d) {
                __nv_bfloat16 ha = __float2bfloat16(va[d]);
                __nv_bfloat16 hb = __float2bfloat16(vb[d]);
                __nv_bfloat16 la = __float2bfloat16(va[d] - __bfloat162float(ha));
                __nv_bfloat16 lb = __float2bfloat16(vb[d] - __bfloat162float(hb));
                *(uint32_t*)(sm + P_VH + (d0 + d) * S2 + s0 * 2) = pack2(ha, hb);
                *(uint32_t*)(sm + P_VL + (d0 + d) * S2 + s0 * 2) = pack2(la, lb);
            }
        }
        __syncthreads();

        // PV MMA
        #pragma unroll
        for (int kt = 0; kt < 8; ++kt) {
            uint32_t awh[2][4], awl[2][4];
            #pragma unroll
            for (int mi = 0; mi < 2; ++mi) {
                uint32_t ra = sb + P_WH + (uint32_t)((wm * 32 + mi * 16 + (lane & 15)) * S2
                             + (lane >> 4) * 16 + kt * 32);
                LDSM4(awh[mi], ra);
                LDSM4(awl[mi], ra + (P_WL - P_WH));
            }
            uint32_t bvh[4], bvl[4];
            {
                uint32_t addr = sb + P_VH + (uint32_t)((wn * 16 + (lane & 15)) * S2
                               + (lane >> 4) * 16 + kt * 32);
                LDSM4(bvh, addr);
                LDSM4(bvl, addr + (P_VL - P_VH));
            }
            #pragma unroll
            for (int q = 0; q < 2; ++q) {
                uint32_t b0h = bvh[q], b1h = bvh[q + 2];
                uint32_t b0l = bvl[q], b1l = bvl[q + 2];
                #pragma unroll
                for (int mi = 0; mi < 2; ++mi) {
                    float* c = accO[mi][q];
                    mma_bf16(c, awh[mi], b0h, b1h);
                    mma_bf16(c, awh[mi], b0l, b1l);
                    mma_bf16(c, awl[mi], b0h, b1h);
                }
            }
        }
    }

    // ---- O epilogue ----
    #pragma unroll
    for (int mi = 0; mi < 2; ++mi) {
        int r0 = qb + wm * 32 + mi * 16 + gid;
        #pragma unroll
        for (int ni = 0; ni < 2; ++ni) {
            int c = wn * 16 + ni * 8 + tig * 2;
            *(float2*)(outO + ((size_t)bh * SEQ + r0) * DH + c) =
                make_float2(accO[mi][ni][0], accO[mi][ni][1]);
            *(float2*)(outO + ((size_t)bh * SEQ + r0 + 8) * DH + c) =
                make_float2(accO[mi][ni][2], accO[mi][ni][3]);
        }
    }
}

extern "C" void kernel_launch(void* const* d_in, const int* in_sizes, int n_in,
                              void* d_out, int out_size) {
    const float* Q    = (const float*)d_in[0];
    const float* K    = (const float*)d_in[1];
    const float* V    = (const float*)d_in[2];
    const float* bias = (const float*)d_in[3];
    float* outO = (float*)d_out;
    float* outW = outO + (size_t)NBH * SEQ * DH;

    static int inited = 0;
    if (!inited) {
        cudaFuncSetAttribute(attn_fused, cudaFuncAttributeMaxDynamicSharedMemorySize, SMEM_TOTAL);
        inited = 1;
    }
    dim3 grid(SEQ / MT, NBH);
    attn_fused<<<grid, 512, SMEM_TOTAL>>>(Q, K, V, bias, outO, outW);
}

// round 10
// speedup vs baseline: 1.1308x; 1.1308x over previous
#include <cuda_runtime.h>
#include <cuda_bf16.h>
#include <cstdint>

#define SEQ 1024
#define DH  64
#define NBH 64
#define MT  128

#define S1  144    // bytes/row: 64 bf16 cols (128B) + 16B pad

// smem (bytes). Phase 2 overlays phase 1 regions.
#define P_QH 0
#define P_QL 18432
#define P_K  36864          // K buf b: H at P_K + b*36864, L at +18432
#define P_W  0              // W buf b: H at b*36864, L at +18432
#define P_V  73728          // V buf b: H at P_V + b*18432, L at +9216
#define ST_SUM 110592
#define ST_INV 114688
#define SMEM_TOTAL 115712

__device__ __forceinline__ uint32_t sm_u32(const void* p) {
    uint32_t a;
    asm("{ .reg .u64 t; cvta.to.shared.u64 t, %1; cvt.u32.u64 %0, t; }" : "=r"(a) : "l"(p));
    return a;
}
__device__ __forceinline__ uint32_t pack2(__nv_bfloat16 a, __nv_bfloat16 b) {
    return (uint32_t)__bfloat16_as_ushort(a) | ((uint32_t)__bfloat16_as_ushort(b) << 16);
}
__device__ __forceinline__ void split4(float4 v, uint2& h, uint2& l) {
    __nv_bfloat16 h0 = __float2bfloat16(v.x), h1 = __float2bfloat16(v.y);
    __nv_bfloat16 h2 = __float2bfloat16(v.z), h3 = __float2bfloat16(v.w);
    __nv_bfloat16 l0 = __float2bfloat16(v.x - __bfloat162float(h0));
    __nv_bfloat16 l1 = __float2bfloat16(v.y - __bfloat162float(h1));
    __nv_bfloat16 l2 = __float2bfloat16(v.z - __bfloat162float(h2));
    __nv_bfloat16 l3 = __float2bfloat16(v.w - __bfloat162float(h3));
    h.x = pack2(h0, h1); h.y = pack2(h2, h3);
    l.x = pack2(l0, l1); l.y = pack2(l2, l3);
}

#define LDSM4(a, addr) \
    asm volatile("ldmatrix.sync.aligned.m8n8.x4.shared.b16 {%0,%1,%2,%3}, [%4];" \
        : "=r"((a)[0]), "=r"((a)[1]), "=r"((a)[2]), "=r"((a)[3]) : "r"(addr))

__device__ __forceinline__ void mma_bf16(float* c, const uint32_t* a, uint32_t b0, uint32_t b1) {
    asm volatile("mma.sync.aligned.m16n8k16.row.col.f32.bf16.bf16.f32 "
        "{%0,%1,%2,%3}, {%4,%5,%6,%7}, {%8,%9}, {%0,%1,%2,%3};"
        : "+f"(c[0]), "+f"(c[1]), "+f"(c[2]), "+f"(c[3])
        : "r"(a[0]), "r"(a[1]), "r"(a[2]), "r"(a[3]), "r"(b0), "r"(b1));
}

__global__ __launch_bounds__(256, 1)
void attn_fused(const float* __restrict__ Qg, const float* __restrict__ Kg,
                const float* __restrict__ Vg, const float* __restrict__ bias,
                float* __restrict__ outO, float* __restrict__ outW)
{
    extern __shared__ char sm[];
    const uint32_t sb = sm_u32(sm);
    const int tid = threadIdx.x;
    const int lane = tid & 31, wid = tid >> 5;
    const int gid = lane >> 2, tig = lane & 3;
    const int wm = wid >> 1, wn = wid & 1;     // 4 x 2 warp grid
    const int bh = blockIdx.y, qb = blockIdx.x * MT;

    const float* Kbase = Kg + (size_t)bh * SEQ * DH;
    const int rK = tid >> 1, cK = (tid & 1) * 32;   // 128-row x 64-col load mapping

    // ---- Q tile: pre-scale + split ----
    {
        const float* Qp = Qg + ((size_t)bh * SEQ + qb) * DH;
        #pragma unroll
        for (int j = 0; j < 8; ++j) {
            float4 v = *(const float4*)(Qp + rK * DH + cK + j * 4);
            v.x *= 0.125f; v.y *= 0.125f; v.z *= 0.125f; v.w *= 0.125f;
            uint2 h, l; split4(v, h, l);
            *(uint2*)(sm + P_QH + rK * S1 + (cK + j * 4) * 2) = h;
            *(uint2*)(sm + P_QL + rK * S1 + (cK + j * 4) * 2) = l;
        }
    }
    // ---- K chunk 0 -> split buf 0 ----
    {
        #pragma unroll
        for (int j = 0; j < 8; ++j) {
            float4 v = *(const float4*)(Kbase + rK * DH + cK + j * 4);
            uint2 h, l; split4(v, h, l);
            *(uint2*)(sm + P_K + rK * S1 + (cK + j * 4) * 2) = h;
            *(uint2*)(sm + P_K + 18432 + rK * S1 + (cK + j * 4) * 2) = l;
        }
    }
    __syncthreads();

    // ---- preload Q fragments ----
    uint32_t aqh[4][2][4], aql[4][2][4];
    #pragma unroll
    for (int kt = 0; kt < 4; ++kt)
        #pragma unroll
        for (int mi = 0; mi < 2; ++mi) {
            uint32_t ra = sb + P_QH + (uint32_t)((wm * 32 + mi * 16 + (lane & 15)) * S1
                         + (lane >> 4) * 16 + kt * 32);
            LDSM4(aqh[kt][mi], ra);
            LDSM4(aql[kt][mi], ra + (P_QL - P_QH));
        }

    // ================= phase 1: E = exp(S) -> outW, row sums =================
    float rs[2][2] = {{0.f, 0.f}, {0.f, 0.f}};

    for (int nc = 0; nc < 8; ++nc) {
        __syncthreads();
        float kraw[32];
        if (nc < 7) {
            const float* Kp = Kbase + (size_t)(nc + 1) * MT * DH;
            #pragma unroll
            for (int j = 0; j < 8; ++j)
                *(float4*)(kraw + j * 4) = *(const float4*)(Kp + rK * DH + cK + j * 4);
        }

        float acc[2][8][4];
        #pragma unroll
        for (int mi = 0; mi < 2; ++mi)
            #pragma unroll
            for (int ni = 0; ni < 8; ++ni)
                #pragma unroll
                for (int e = 0; e < 4; ++e) acc[mi][ni][e] = 0.f;

        const uint32_t kb = sb + P_K + (uint32_t)(nc & 1) * 36864;
        #pragma unroll
        for (int kt = 0; kt < 4; ++kt) {
            #pragma unroll
            for (int p = 0; p < 4; ++p) {
                uint32_t addr = kb + (uint32_t)((wn * 64 + p * 16 + (lane & 15)) * S1
                               + (lane >> 4) * 16 + kt * 32);
                uint32_t bh4[4], bl4[4];
                LDSM4(bh4, addr);
                LDSM4(bl4, addr + 18432);
                #pragma unroll
                for (int q = 0; q < 2; ++q)
                    #pragma unroll
                    for (int mi = 0; mi < 2; ++mi) {
                        float* c = acc[mi][p * 2 + q];
                        mma_bf16(c, aqh[kt][mi], bh4[q], bh4[q + 2]);
                        mma_bf16(c, aqh[kt][mi], bl4[q], bl4[q + 2]);
                        mma_bf16(c, aql[kt][mi], bh4[q], bh4[q + 2]);
                    }
            }
        }

        if (nc < 7) {
            char* kh = sm + P_K + ((nc + 1) & 1) * 36864;
            #pragma unroll
            for (int j = 0; j < 8; ++j) {
                uint2 h, l; split4(*(float4*)(kraw + j * 4), h, l);
                *(uint2*)(kh + rK * S1 + (cK + j * 4) * 2) = h;
                *(uint2*)(kh + 18432 + rK * S1 + (cK + j * 4) * 2) = l;
            }
        }

        #pragma unroll
        for (int mi = 0; mi < 2; ++mi) {
            int r0 = qb + wm * 32 + mi * 16 + gid;
            #pragma unroll
            for (int ni = 0; ni < 8; ++ni) {
                int c = nc * 128 + wn * 64 + ni * 8 + tig * 2;
                float2 b0 = *(const float2*)(bias + (size_t)r0 * SEQ + c);
                float e0 = __expf(acc[mi][ni][0] + b0.x);
                float e1 = __expf(acc[mi][ni][1] + b0.y);
                *(float2*)(outW + ((size_t)bh * SEQ + r0) * SEQ + c) = make_float2(e0, e1);
                rs[mi][0] += e0 + e1;
                float2 b1 = *(const float2*)(bias + (size_t)(r0 + 8) * SEQ + c);
                float e2 = __expf(acc[mi][ni][2] + b1.x);
                float e3 = __expf(acc[mi][ni][3] + b1.y);
                *(float2*)(outW + ((size_t)bh * SEQ + r0 + 8) * SEQ + c) = make_float2(e2, e3);
                rs[mi][1] += e2 + e3;
            }
        }
    }

    // ---- reduce per-row sums -> 1/sum ----
    {
        float* st = (float*)(sm + ST_SUM);
        int slot = wn * 4 + tig;
        #pragma unroll
        for (int mi = 0; mi < 2; ++mi)
            #pragma unroll
            for (int h = 0; h < 2; ++h)
                st[(wm * 32 + mi * 16 + h * 8 + gid) * 8 + slot] = rs[mi][h];
    }
    __syncthreads();
    if (tid < 128) {
        float* st = (float*)(sm + ST_SUM);
        float s = 0.f;
        #pragma unroll
        for (int i = 0; i < 8; ++i) s += st[tid * 8 + i];
        ((float*)(sm + ST_INV))[tid] = 1.f / s;
    }
    __syncthreads();

    const float invR = ((const float*)(sm + ST_INV))[rK];
    float* Wbase = outW + ((size_t)bh * SEQ + qb) * SEQ;
    const float* Vbase = Vg + (size_t)bh * SEQ * DH;
    const int s0 = (tid & 31) * 2, d0 = (tid >> 5) * 8;
    const int cW = cK & 31;          // 0 or 32 within 64-col chunk? (cK is 0/32)

    // ---- phase 2 prologue: chunk 0 ----
    {
        float* Ep = Wbase + (size_t)rK * SEQ + cK;
        #pragma unroll
        for (int j = 0; j < 8; ++j) {
            float4 e = *(float4*)(Ep + j * 4);
            float4 w = make_float4(e.x * invR, e.y * invR, e.z * invR, e.w * invR);
            *(float4*)(Ep + j * 4) = w;
            uint2 h, l; split4(w, h, l);
            *(uint2*)(sm + P_W + rK * S1 + (cK + j * 4) * 2) = h;
            *(uint2*)(sm + P_W + 18432 + rK * S1 + (cK + j * 4) * 2) = l;
        }
        const float* vp = Vbase + (size_t)s0 * DH + d0;
        float va[8], vb[8];
        *(float4*)(va)     = *(const float4*)(vp);
        *(float4*)(va + 4) = *(const float4*)(vp + 4);
        *(float4*)(vb)     = *(const float4*)(vp + DH);
        *(float4*)(vb + 4) = *(const float4*)(vp + DH + 4);
        #pragma unroll
        for (int d = 0; d < 8; ++d) {
            __nv_bfloat16 ha = __float2bfloat16(va[d]);
            __nv_bfloat16 hb = __float2bfloat16(vb[d]);
            __nv_bfloat16 la = __float2bfloat16(va[d] - __bfloat162float(ha));
            __nv_bfloat16 lb = __float2bfloat16(vb[d] - __bfloat162float(hb));
            *(uint32_t*)(sm + P_V + (d0 + d) * S1 + s0 * 2) = pack2(ha, hb);
            *(uint32_t*)(sm + P_V + 9216 + (d0 + d) * S1 + s0 * 2) = pack2(la, lb);
        }
    }

    // ================= phase 2: O = W @ V =================
    float accO[2][4][4];
    #pragma unroll
    for (int mi = 0; mi < 2; ++mi)
        #pragma unroll
        for (int ni = 0; ni < 4; ++ni)
            #pragma unroll
            for (int e = 0; e < 4; ++e) accO[mi][ni][e] = 0.f;

    for (int nc = 0; nc < 16; ++nc) {
        __syncthreads();
        float eraw[32];
        float va[8], vb[8];
        if (nc < 15) {
            const float* Ep = Wbase + (size_t)rK * SEQ + (nc + 1) * 64 + cK;
            #pragma unroll
            for (int j = 0; j < 8; ++j)
                *(float4*)(eraw + j * 4) = *(const float4*)(Ep + j * 4);
            const float* vp = Vbase + (size_t)((nc + 1) * 64 + s0) * DH + d0;
            *(float4*)(va)     = *(const float4*)(vp);
            *(float4*)(va + 4) = *(const float4*)(vp + 4);
            *(float4*)(vb)     = *(const float4*)(vp + DH);
            *(float4*)(vb + 4) = *(const float4*)(vp + DH + 4);
        }

        const uint32_t wbuf = sb + P_W + (uint32_t)(nc & 1) * 36864;
        const uint32_t vbuf = sb + P_V + (uint32_t)(nc & 1) * 18432;
        #pragma unroll
        for (int kt = 0; kt < 4; ++kt) {
            uint32_t awh[2][4], awl[2][4];
            #pragma unroll
            for (int mi = 0; mi < 2; ++mi) {
                uint32_t ra = wbuf + (uint32_t)((wm * 32 + mi * 16 + (lane & 15)) * S1
                             + (lane >> 4) * 16 + kt * 32);
                LDSM4(awh[mi], ra);
                LDSM4(awl[mi], ra + 18432);
            }
            uint32_t bvh[2][4], bvl[2][4];
            #pragma unroll
            for (int p = 0; p < 2; ++p) {
                uint32_t addr = vbuf + (uint32_t)((wn * 32 + p * 16 + (lane & 15)) * S1
                               + (lane >> 4) * 16 + kt * 32);
                LDSM4(bvh[p], addr);
                LDSM4(bvl[p], addr + 9216);
            }
            #pragma unroll
            for (int p = 0; p < 2; ++p)
                #pragma unroll
                for (int q = 0; q < 2; ++q)
                    #pragma unroll
                    for (int mi = 0; mi < 2; ++mi) {
                        float* c = accO[mi][p * 2 + q];
                        mma_bf16(c, awh[mi], bvh[p][q], bvh[p][q + 2]);
                        mma_bf16(c, awh[mi], bvl[p][q], bvl[p][q + 2]);
                        mma_bf16(c, awl[mi], bvh[p][q], bvh[p][q + 2]);
                    }
        }

        if (nc < 15) {
            float* Ewp = Wbase + (size_t)rK * SEQ + (nc + 1) * 64 + cK;
            char* wh = sm + P_W + ((nc + 1) & 1) * 36864;
            #pragma unroll
            for (int j = 0; j < 8; ++j) {
                float4 e = *(float4*)(eraw + j * 4);
                float4 w = make_float4(e.x * invR, e.y * invR, e.z * invR, e.w * invR);
                *(float4*)(Ewp + j * 4) = w;
                uint2 h, l; split4(w, h, l);
                *(uint2*)(wh + rK * S1 + (cK + j * 4) * 2) = h;
                *(uint2*)(wh + 18432 + rK * S1 + (cK + j * 4) * 2) = l;
            }
            char* vh = sm + P_V + ((nc + 1) & 1) * 18432;
            #pragma unroll
            for (int d = 0; d < 8; ++d) {
                __nv_bfloat16 ha = __float2bfloat16(va[d]);
                __nv_bfloat16 hb = __float2bfloat16(vb[d]);
                __nv_bfloat16 la = __float2bfloat16(va[d] - __bfloat162float(ha));
                __nv_bfloat16 lb = __float2bfloat16(vb[d] - __bfloat162float(hb));
                *(uint32_t*)(vh + (d0 + d) * S1 + s0 * 2) = pack2(ha, hb);
                *(uint32_t*)(vh + 9216 + (d0 + d) * S1 + s0 * 2) = pack2(la, lb);
            }
        }
    }

    // ---- O epilogue ----
    #pragma unroll
    for (int mi = 0; mi < 2; ++mi) {
        int r0 = qb + wm * 32 + mi * 16 + gid;
        #pragma unroll
        for (int ni = 0; ni < 4; ++ni) {
            int c = wn * 32 + ni * 8 + tig * 2;
            *(float2*)(outO + ((size_t)bh * SEQ + r0) * DH + c) =
                make_float2(accO[mi][ni][0], accO[mi][ni][1]);
            *(float2*)(outO + ((size_t)bh * SEQ + r0 + 8) * DH + c) =
                make_float2(accO[mi][ni][2], accO[mi][ni][3]);
        }
    }
}

extern "C" void kernel_launch(void* const* d_in, const int* in_sizes, int n_in,
                              void* d_out, int out_size) {
    const float* Q    = (const float*)d_in[0];
    const float* K    = (const float*)d_in[1];
    const float* V    = (const float*)d_in[2];
    const float* bias = (const float*)d_in[3];
    float* outO = (float*)d_out;
    float* outW = outO + (size_t)NBH * SEQ * DH;

    static int inited = 0;
    if (!inited) {
        cudaFuncSetAttribute(attn_fused, cudaFuncAttributeMaxDynamicSharedMemorySize, SMEM_TOTAL);
        inited = 1;
    }
    dim3 grid(SEQ / MT, NBH);
    attn_fused<<<grid, 256, SMEM_TOTAL>>>(Q, K, V, bias, outO, outW);
}

// round 14
// speedup vs baseline: 1.2094x; 1.0695x over previous
#include <cuda_runtime.h>
#include <cuda_bf16.h>
#include <cstdint>

#define SEQ 1024
#define DH  64
#define NBH 64
#define MT  128

#define S1  144    // bytes/row: 64 bf16 cols (128B) + 16B pad

// smem (bytes). Phase 2 overlays phase 1 regions.
#define P_QH 0
#define P_QL 18432
#define P_K  36864          // K buf b: H at P_K + b*36864, L at +18432
#define P_W  0              // W buf b: H at b*36864, L at +18432
#define P_V  73728          // V buf b: H at P_V + b*18432, L at +9216
#define ST_SUM 110592       // 128*16 floats = 8 KB
#define ST_INV 118784       // 128 floats
#define SMEM_TOTAL 119808

__device__ __forceinline__ uint32_t sm_u32(const void* p) {
    uint32_t a;
    asm("{ .reg .u64 t; cvta.to.shared.u64 t, %1; cvt.u32.u64 %0, t; }" : "=r"(a) : "l"(p));
    return a;
}
__device__ __forceinline__ uint32_t pack2(__nv_bfloat16 a, __nv_bfloat16 b) {
    return (uint32_t)__bfloat16_as_ushort(a) | ((uint32_t)__bfloat16_as_ushort(b) << 16);
}
__device__ __forceinline__ void split4(float4 v, uint2& h, uint2& l) {
    __nv_bfloat16 h0 = __float2bfloat16(v.x), h1 = __float2bfloat16(v.y);
    __nv_bfloat16 h2 = __float2bfloat16(v.z), h3 = __float2bfloat16(v.w);
    __nv_bfloat16 l0 = __float2bfloat16(v.x - __bfloat162float(h0));
    __nv_bfloat16 l1 = __float2bfloat16(v.y - __bfloat162float(h1));
    __nv_bfloat16 l2 = __float2bfloat16(v.z - __bfloat162float(h2));
    __nv_bfloat16 l3 = __float2bfloat16(v.w - __bfloat162float(h3));
    h.x = pack2(h0, h1); h.y = pack2(h2, h3);
    l.x = pack2(l0, l1); l.y = pack2(l2, l3);
}

#define LDSM4(a, addr) \
    asm volatile("ldmatrix.sync.aligned.m8n8.x4.shared.b16 {%0,%1,%2,%3}, [%4];" \
        : "=r"((a)[0]), "=r"((a)[1]), "=r"((a)[2]), "=r"((a)[3]) : "r"(addr))

__device__ __forceinline__ void mma_bf16(float* c, const uint32_t* a, uint32_t b0, uint32_t b1) {
    asm volatile("mma.sync.aligned.m16n8k16.row.col.f32.bf16.bf16.f32 "
        "{%0,%1,%2,%3}, {%4,%5,%6,%7}, {%8,%9}, {%0,%1,%2,%3};"
        : "+f"(c[0]), "+f"(c[1]), "+f"(c[2]), "+f"(c[3])
        : "r"(a[0]), "r"(a[1]), "r"(a[2]), "r"(a[3]), "r"(b0), "r"(b1));
}

__global__ __launch_bounds__(512, 1)
void attn_fused(const float* __restrict__ Qg, const float* __restrict__ Kg,
                const float* __restrict__ Vg, const float* __restrict__ bias,
                float* __restrict__ outO, float* __restrict__ outW)
{
    extern __shared__ char sm[];
    const uint32_t sb = sm_u32(sm);
    const int tid = threadIdx.x;
    const int lane = tid & 31, wid = tid >> 5;
    const int gid = lane >> 2, tig = lane & 3;
    const int wm = wid >> 2, wn = wid & 3;         // 4 x 4 warp grid
    const int bh = blockIdx.y, qb = blockIdx.x * MT;

    const float* Kbase = Kg + (size_t)bh * SEQ * DH;
    const int rK = tid >> 2, cK = (tid & 3) * 16;   // 128-row x 64-col load map (16 floats/thread)

    // ---- Q tile: pre-scale + split ----
    {
        const float* Qp = Qg + ((size_t)bh * SEQ + qb) * DH;
        #pragma unroll
        for (int j = 0; j < 4; ++j) {
            float4 v = *(const float4*)(Qp + rK * DH + cK + j * 4);
            v.x *= 0.125f; v.y *= 0.125f; v.z *= 0.125f; v.w *= 0.125f;
            uint2 h, l; split4(v, h, l);
            *(uint2*)(sm + P_QH + rK * S1 + (cK + j * 4) * 2) = h;
            *(uint2*)(sm + P_QL + rK * S1 + (cK + j * 4) * 2) = l;
        }
    }
    // ---- K chunk 0 -> split buf 0 ----
    {
        #pragma unroll
        for (int j = 0; j < 4; ++j) {
            float4 v = *(const float4*)(Kbase + rK * DH + cK + j * 4);
            uint2 h, l; split4(v, h, l);
            *(uint2*)(sm + P_K + rK * S1 + (cK + j * 4) * 2) = h;
            *(uint2*)(sm + P_K + 18432 + rK * S1 + (cK + j * 4) * 2) = l;
        }
    }
    __syncthreads();

    // ---- preload Q fragments ----
    uint32_t aqh[4][2][4], aql[4][2][4];
    #pragma unroll
    for (int kt = 0; kt < 4; ++kt)
        #pragma unroll
        for (int mi = 0; mi < 2; ++mi) {
            uint32_t ra = sb + P_QH + (uint32_t)((wm * 32 + mi * 16 + (lane & 15)) * S1
                         + (lane >> 4) * 16 + kt * 32);
            LDSM4(aqh[kt][mi], ra);
            LDSM4(aql[kt][mi], ra + (P_QL - P_QH));
        }

    // ================= phase 1: E = exp(S) -> outW, row sums =================
    float rs[2][2] = {{0.f, 0.f}, {0.f, 0.f}};

    for (int nc = 0; nc < 8; ++nc) {
        __syncthreads();
        float kraw[16];
        if (nc < 7) {
            const float* Kp = Kbase + (size_t)(nc + 1) * MT * DH;
            #pragma unroll
            for (int j = 0; j < 4; ++j)
                *(float4*)(kraw + j * 4) = *(const float4*)(Kp + rK * DH + cK + j * 4);
        }

        float acc[2][4][4];
        #pragma unroll
        for (int mi = 0; mi < 2; ++mi)
            #pragma unroll
            for (int ni = 0; ni < 4; ++ni)
                #pragma unroll
                for (int e = 0; e < 4; ++e) acc[mi][ni][e] = 0.f;

        const uint32_t kb = sb + P_K + (uint32_t)(nc & 1) * 36864;
        #pragma unroll
        for (int kt = 0; kt < 4; ++kt) {
            #pragma unroll
            for (int p = 0; p < 2; ++p) {
                uint32_t addr = kb + (uint32_t)((wn * 32 + p * 16 + (lane & 15)) * S1
                               + (lane >> 4) * 16 + kt * 32);
                uint32_t bh4[4], bl4[4];
                LDSM4(bh4, addr);
                LDSM4(bl4, addr + 18432);
                #pragma unroll
                for (int q = 0; q < 2; ++q)
                    #pragma unroll
                    for (int mi = 0; mi < 2; ++mi) {
                        float* c = acc[mi][p * 2 + q];
                        mma_bf16(c, aqh[kt][mi], bh4[q], bh4[q + 2]);
                        mma_bf16(c, aqh[kt][mi], bl4[q], bl4[q + 2]);
                        mma_bf16(c, aql[kt][mi], bh4[q], bh4[q + 2]);
                    }
            }
        }

        if (nc < 7) {
            char* kh = sm + P_K + ((nc + 1) & 1) * 36864;
            #pragma unroll
            for (int j = 0; j < 4; ++j) {
                uint2 h, l; split4(*(float4*)(kraw + j * 4), h, l);
                *(uint2*)(kh + rK * S1 + (cK + j * 4) * 2) = h;
                *(uint2*)(kh + 18432 + rK * S1 + (cK + j * 4) * 2) = l;
            }
        }

        #pragma unroll
        for (int mi = 0; mi < 2; ++mi) {
            int r0 = qb + wm * 32 + mi * 16 + gid;
            #pragma unroll
            for (int ni = 0; ni < 4; ++ni) {
                int c = nc * 128 + wn * 32 + ni * 8 + tig * 2;
                float2 b0 = *(const float2*)(bias + (size_t)r0 * SEQ + c);
                float e0 = __expf(acc[mi][ni][0] + b0.x);
                float e1 = __expf(acc[mi][ni][1] + b0.y);
                *(float2*)(outW + ((size_t)bh * SEQ + r0) * SEQ + c) = make_float2(e0, e1);
                rs[mi][0] += e0 + e1;
                float2 b1 = *(const float2*)(bias + (size_t)(r0 + 8) * SEQ + c);
                float e2 = __expf(acc[mi][ni][2] + b1.x);
                float e3 = __expf(acc[mi][ni][3] + b1.y);
                *(float2*)(outW + ((size_t)bh * SEQ + r0 + 8) * SEQ + c) = make_float2(e2, e3);
                rs[mi][1] += e2 + e3;
            }
        }
    }

    // ---- reduce per-row sums -> 1/sum ----
    {
        float* st = (float*)(sm + ST_SUM);
        int slot = wn * 4 + tig;
        #pragma unroll
        for (int mi = 0; mi < 2; ++mi)
            #pragma unroll
            for (int h = 0; h < 2; ++h)
                st[(wm * 32 + mi * 16 + h * 8 + gid) * 16 + slot] = rs[mi][h];
    }
    __syncthreads();
    if (tid < 128) {
        float* st = (float*)(sm + ST_SUM);
        float s = 0.f;
        #pragma unroll
        for (int i = 0; i < 16; ++i) s += st[tid * 16 + i];
        ((float*)(sm + ST_INV))[tid] = 1.f / s;
    }
    __syncthreads();

    const float invR = ((const float*)(sm + ST_INV))[rK];
    float* Wbase = outW + ((size_t)bh * SEQ + qb) * SEQ;
    const float* Vbase = Vg + (size_t)bh * SEQ * DH;
    const int s0 = (tid & 31) * 2, d0 = (tid >> 5) * 4;   // V: 64 s-rows x 64 d-cols

    // ---- phase 2 prologue: chunk 0 ----
    {
        float* Ep = Wbase + (size_t)rK * SEQ + cK;
        #pragma unroll
        for (int j = 0; j < 4; ++j) {
            float4 e = *(float4*)(Ep + j * 4);
            float4 w = make_float4(e.x * invR, e.y * invR, e.z * invR, e.w * invR);
            *(float4*)(Ep + j * 4) = w;
            uint2 h, l; split4(w, h, l);
            *(uint2*)(sm + P_W + rK * S1 + (cK + j * 4) * 2) = h;
            *(uint2*)(sm + P_W + 18432 + rK * S1 + (cK + j * 4) * 2) = l;
        }
        const float* vp = Vbase + (size_t)s0 * DH + d0;
        float4 va = *(const float4*)(vp);
        float4 vb = *(const float4*)(vp + DH);
        float fa[4] = {va.x, va.y, va.z, va.w};
        float fb[4] = {vb.x, vb.y, vb.z, vb.w};
        #pragma unroll
        for (int d = 0; d < 4; ++d) {
            __nv_bfloat16 ha = __float2bfloat16(fa[d]);
            __nv_bfloat16 hb = __float2bfloat16(fb[d]);
            __nv_bfloat16 la = __float2bfloat16(fa[d] - __bfloat162float(ha));
            __nv_bfloat16 lb = __float2bfloat16(fb[d] - __bfloat162float(hb));
            *(uint32_t*)(sm + P_V + (d0 + d) * S1 + s0 * 2) = pack2(ha, hb);
            *(uint32_t*)(sm + P_V + 9216 + (d0 + d) * S1 + s0 * 2) = pack2(la, lb);
        }
    }

    // ================= phase 2: O = W @ V =================
    float accO[2][2][4];
    #pragma unroll
    for (int mi = 0; mi < 2; ++mi)
        #pragma unroll
        for (int ni = 0; ni < 2; ++ni)
            #pragma unroll
            for (int e = 0; e < 4; ++e) accO[mi][ni][e] = 0.f;

    for (int nc = 0; nc < 16; ++nc) {
        __syncthreads();
        float eraw[16];
        float fa[4], fb[4];
        if (nc < 15) {
            const float* Ep = Wbase + (size_t)rK * SEQ + (nc + 1) * 64 + cK;
            #pragma unroll
            for (int j = 0; j < 4; ++j)
                *(float4*)(eraw + j * 4) = *(const float4*)(Ep + j * 4);
            const float* vp = Vbase + (size_t)((nc + 1) * 64 + s0) * DH + d0;
            float4 va = *(const float4*)(vp);
            float4 vb = *(const float4*)(vp + DH);
            fa[0]=va.x; fa[1]=va.y; fa[2]=va.z; fa[3]=va.w;
            fb[0]=vb.x; fb[1]=vb.y; fb[2]=vb.z; fb[3]=vb.w;
        }

        const uint32_t wbuf = sb + P_W + (uint32_t)(nc & 1) * 36864;
        const uint32_t vbuf = sb + P_V + (uint32_t)(nc & 1) * 18432;
        #pragma unroll
        for (int kt = 0; kt < 4; ++kt) {
            uint32_t awh[2][4], awl[2][4];
            #pragma unroll
            for (int mi = 0; mi < 2; ++mi) {
                uint32_t ra = wbuf + (uint32_t)((wm * 32 + mi * 16 + (lane & 15)) * S1
                             + (lane >> 4) * 16 + kt * 32);
                LDSM4(awh[mi], ra);
                LDSM4(awl[mi], ra + 18432);
            }
            uint32_t bvh[4], bvl[4];
            {
                uint32_t addr = vbuf + (uint32_t)((wn * 16 + (lane & 15)) * S1
                               + (lane >> 4) * 16 + kt * 32);
                LDSM4(bvh, addr);
                LDSM4(bvl, addr + 9216);
            }
            #pragma unroll
            for (int q = 0; q < 2; ++q)
                #pragma unroll
                for (int mi = 0; mi < 2; ++mi) {
                    float* c = accO[mi][q];
                    mma_bf16(c, awh[mi], bvh[q], bvh[q + 2]);
                    mma_bf16(c, awh[mi], bvl[q], bvl[q + 2]);
                    mma_bf16(c, awl[mi], bvh[q], bvh[q + 2]);
                }
        }

        if (nc < 15) {
            float* Ewp = Wbase + (size_t)rK * SEQ + (nc + 1) * 64 + cK;
            char* wh = sm + P_W + ((nc + 1) & 1) * 36864;
            #pragma unroll
            for (int j = 0; j < 4; ++j) {
                float4 e = *(float4*)(eraw + j * 4);
                float4 w = make_float4(e.x * invR, e.y * invR, e.z * invR, e.w * invR);
                *(float4*)(Ewp + j * 4) = w;
                uint2 h, l; split4(w, h, l);
                *(uint2*)(wh + rK * S1 + (cK + j * 4) * 2) = h;
                *(uint2*)(wh + 18432 + rK * S1 + (cK + j * 4) * 2) = l;
            }
            char* vh = sm + P_V + ((nc + 1) & 1) * 18432;
            #pragma unroll
            for (int d = 0; d < 4; ++d) {
                __nv_bfloat16 ha = __float2bfloat16(fa[d]);
                __nv_bfloat16 hb = __float2bfloat16(fb[d]);
                __nv_bfloat16 la = __float2bfloat16(fa[d] - __bfloat162float(ha));
                __nv_bfloat16 lb = __float2bfloat16(fb[d] - __bfloat162float(hb));
                *(uint32_t*)(vh + (d0 + d) * S1 + s0 * 2) = pack2(ha, hb);
                *(uint32_t*)(vh + 9216 + (d0 + d) * S1 + s0 * 2) = pack2(la, lb);
            }
        }
    }

    // ---- O epilogue ----
    #pragma unroll
    for (int mi = 0; mi < 2; ++mi) {
        int r0 = qb + wm * 32 + mi * 16 + gid;
        #pragma unroll
        for (int ni = 0; ni < 2; ++ni) {
            int c = wn * 16 + ni * 8 + tig * 2;
            *(float2*)(outO + ((size_t)bh * SEQ + r0) * DH + c) =
                make_float2(accO[mi][ni][0], accO[mi][ni][1]);
            *(float2*)(outO + ((size_t)bh * SEQ + r0 + 8) * DH + c) =
                make_float2(accO[mi][ni][2], accO[mi][ni][3]);
        }
    }
}

extern "C" void kernel_launch(void* const* d_in, const int* in_sizes, int n_in,
                              void* d_out, int out_size) {
    const float* Q    = (const float*)d_in[0];
    const float* K    = (const float*)d_in[1];
    const float* V    = (const float*)d_in[2];
    const float* bias = (const float*)d_in[3];
    float* outO = (float*)d_out;
    float* outW = outO + (size_t)NBH * SEQ * DH;

    static int inited = 0;
    if (!inited) {
        cudaFuncSetAttribute(attn_fused, cudaFuncAttributeMaxDynamicSharedMemorySize, SMEM_TOTAL);
        inited = 1;
    }
    dim3 grid(SEQ / MT, NBH);
    attn_fused<<<grid, 512, SMEM_TOTAL>>>(Q, K, V, bias, outO, outW);
}

// round 16
// speedup vs baseline: 1.3234x; 1.0943x over previous
#include <cuda_runtime.h>
#include <cuda_bf16.h>
#include <cstdint>

#define SEQ 1024
#define DH  64
#define NBH 64
#define MT  128
#define NC  64

#define S1  144    // bytes/row: 64 bf16 cols (128B) + 16B pad (conflict-free: 36 banks)

// smem layout (bytes)
#define P_QH 0                  // 128 x 64 bf16 hi  (18432)
#define P_QL 18432              // lo
#define P_K  36864              // K buf b at +b*18432: H 9216 | L 9216   (64 rows)
#define P_W  73728              // W tile: H 18432 | L 18432  (128 rows x 64 cols)
#define P_V  110592             // V buf b at +b*18432: H 9216 | L 9216  ([d][s] 64x64)
#define ST_SUM 147456           // 128*16 floats
#define ST_INV 155648           // 128 floats
#define SMEM_TOTAL 156160

__device__ float g_inv[NBH * SEQ];

__device__ __forceinline__ uint32_t sm_u32(const void* p) {
    uint32_t a;
    asm("{ .reg .u64 t; cvta.to.shared.u64 t, %1; cvt.u32.u64 %0, t; }" : "=r"(a) : "l"(p));
    return a;
}
__device__ __forceinline__ uint32_t pack2(__nv_bfloat16 a, __nv_bfloat16 b) {
    return (uint32_t)__bfloat16_as_ushort(a) | ((uint32_t)__bfloat16_as_ushort(b) << 16);
}
__device__ __forceinline__ void split4(float4 v, uint2& h, uint2& l) {
    __nv_bfloat16 h0 = __float2bfloat16(v.x), h1 = __float2bfloat16(v.y);
    __nv_bfloat16 h2 = __float2bfloat16(v.z), h3 = __float2bfloat16(v.w);
    __nv_bfloat16 l0 = __float2bfloat16(v.x - __bfloat162float(h0));
    __nv_bfloat16 l1 = __float2bfloat16(v.y - __bfloat162float(h1));
    __nv_bfloat16 l2 = __float2bfloat16(v.z - __bfloat162float(h2));
    __nv_bfloat16 l3 = __float2bfloat16(v.w - __bfloat162float(h3));
    h.x = pack2(h0, h1); h.y = pack2(h2, h3);
    l.x = pack2(l0, l1); l.y = pack2(l2, l3);
}

#define LDSM4(a, addr) \
    asm volatile("ldmatrix.sync.aligned.m8n8.x4.shared.b16 {%0,%1,%2,%3}, [%4];" \
        : "=r"((a)[0]), "=r"((a)[1]), "=r"((a)[2]), "=r"((a)[3]) : "r"(addr))

__device__ __forceinline__ void mma_bf16(float* c, const uint32_t* a, uint32_t b0, uint32_t b1) {
    asm volatile("mma.sync.aligned.m16n8k16.row.col.f32.bf16.bf16.f32 "
        "{%0,%1,%2,%3}, {%4,%5,%6,%7}, {%8,%9}, {%0,%1,%2,%3};"
        : "+f"(c[0]), "+f"(c[1]), "+f"(c[2]), "+f"(c[3])
        : "r"(a[0]), "r"(a[1]), "r"(a[2]), "r"(a[3]), "r"(b0), "r"(b1));
}

__global__ __launch_bounds__(512, 1)
void attn_k1(const float* __restrict__ Qg, const float* __restrict__ Kg,
             const float* __restrict__ Vg, const float* __restrict__ bias,
             float* __restrict__ outO, float* __restrict__ outW)
{
    extern __shared__ char sm[];
    const uint32_t sb = sm_u32(sm);
    const int tid = threadIdx.x;
    const int lane = tid & 31, wid = tid >> 5;
    const int gid = lane >> 2, tig = lane & 3;
    const int wm = wid >> 2, wn = wid & 3;        // 4 x 4 warps; warp tile 32m x 16n
    const int bh = blockIdx.y, qb = blockIdx.x * MT;

    const float* Kbase = Kg + (size_t)bh * SEQ * DH;
    const float* Vbase = Vg + (size_t)bh * SEQ * DH;

    const int rQ = tid >> 2,  cQ = (tid & 3) * 16;   // Q: 128 x 64, 16 f/thread
    const int rK = tid >> 3,  cK = (tid & 7) * 8;    // K: 64 x 64, 8 f/thread
    const int s0 = (tid & 31) * 2, d0 = (tid >> 5) * 4;  // V: 64 s x 64 d, 8 f/thread

    // ---- prologue: Q split; K chunk 0; V chunk 0 ----
    {
        const float* Qp = Qg + ((size_t)bh * SEQ + qb) * DH;
        #pragma unroll
        for (int j = 0; j < 4; ++j) {
            float4 v = *(const float4*)(Qp + rQ * DH + cQ + j * 4);
            v.x *= 0.125f; v.y *= 0.125f; v.z *= 0.125f; v.w *= 0.125f;
            uint2 h, l; split4(v, h, l);
            *(uint2*)(sm + P_QH + rQ * S1 + (cQ + j * 4) * 2) = h;
            *(uint2*)(sm + P_QL + rQ * S1 + (cQ + j * 4) * 2) = l;
        }
        #pragma unroll
        for (int j = 0; j < 2; ++j) {
            float4 v = *(const float4*)(Kbase + rK * DH + cK + j * 4);
            uint2 h, l; split4(v, h, l);
            *(uint2*)(sm + P_K + rK * S1 + (cK + j * 4) * 2) = h;
            *(uint2*)(sm + P_K + 9216 + rK * S1 + (cK + j * 4) * 2) = l;
        }
        const float* vp = Vbase + (size_t)s0 * DH + d0;
        float4 va = *(const float4*)(vp);
        float4 vb = *(const float4*)(vp + DH);
        float fa[4] = {va.x, va.y, va.z, va.w};
        float fb[4] = {vb.x, vb.y, vb.z, vb.w};
        #pragma unroll
        for (int d = 0; d < 4; ++d) {
            __nv_bfloat16 ha = __float2bfloat16(fa[d]);
            __nv_bfloat16 hb = __float2bfloat16(fb[d]);
            __nv_bfloat16 la = __float2bfloat16(fa[d] - __bfloat162float(ha));
            __nv_bfloat16 lb = __float2bfloat16(fb[d] - __bfloat162float(hb));
            *(uint32_t*)(sm + P_V + (d0 + d) * S1 + s0 * 2) = pack2(ha, hb);
            *(uint32_t*)(sm + P_V + 9216 + (d0 + d) * S1 + s0 * 2) = pack2(la, lb);
        }
    }

    float rs[2][2] = {{0.f, 0.f}, {0.f, 0.f}};
    float accO[2][2][4];
    #pragma unroll
    for (int mi = 0; mi < 2; ++mi)
        #pragma unroll
        for (int q = 0; q < 2; ++q)
            #pragma unroll
            for (int e = 0; e < 4; ++e) accO[mi][q][e] = 0.f;

    for (int nc = 0; nc < 16; ++nc) {
        __syncthreads();   // K/V buf[nc&1] + (iter>0) next-buf STS visible; W free

        // prefetch next K/V into regs (hidden under QK MMA)
        float kraw[8];
        float fa[4], fb[4];
        if (nc < 15) {
            const float* Kp = Kbase + (size_t)(nc + 1) * NC * DH;
            *(float4*)(kraw)     = *(const float4*)(Kp + rK * DH + cK);
            *(float4*)(kraw + 4) = *(const float4*)(Kp + rK * DH + cK + 4);
            const float* vp = Vbase + (size_t)((nc + 1) * NC + s0) * DH + d0;
            float4 va = *(const float4*)(vp);
            float4 vb = *(const float4*)(vp + DH);
            fa[0]=va.x; fa[1]=va.y; fa[2]=va.z; fa[3]=va.w;
            fb[0]=vb.x; fb[1]=vb.y; fb[2]=vb.z; fb[3]=vb.w;
        }

        // ---- QK MMA (K buf nc&1) ----
        float acc[2][2][4];
        #pragma unroll
        for (int mi = 0; mi < 2; ++mi)
            #pragma unroll
            for (int q = 0; q < 2; ++q)
                #pragma unroll
                for (int e = 0; e < 4; ++e) acc[mi][q][e] = 0.f;

        const uint32_t kb = sb + P_K + (uint32_t)(nc & 1) * 18432;
        #pragma unroll
        for (int kt = 0; kt < 4; ++kt) {
            uint32_t ah[2][4], al[2][4];
            #pragma unroll
            for (int mi = 0; mi < 2; ++mi) {
                uint32_t ra = sb + P_QH + (uint32_t)((wm * 32 + mi * 16 + (lane & 15)) * S1
                             + (lane >> 4) * 16 + kt * 32);
                LDSM4(ah[mi], ra);
                LDSM4(al[mi], ra + 18432);
            }
            uint32_t bh4[4], bl4[4];
            uint32_t addr = kb + (uint32_t)((wn * 16 + (lane & 15)) * S1
                           + (lane >> 4) * 16 + kt * 32);
            LDSM4(bh4, addr);
            LDSM4(bl4, addr + 9216);
            #pragma unroll
            for (int q = 0; q < 2; ++q)
                #pragma unroll
                for (int mi = 0; mi < 2; ++mi) {
                    float* c = acc[mi][q];
                    mma_bf16(c, ah[mi], bh4[q], bh4[q + 2]);
                    mma_bf16(c, ah[mi], bl4[q], bl4[q + 2]);
                    mma_bf16(c, al[mi], bh4[q], bh4[q + 2]);
                }
        }

        // ---- epilogue: E = exp(S+bias) -> gmem + smem split; row sums ----
        #pragma unroll
        for (int mi = 0; mi < 2; ++mi) {
            int r0 = qb + wm * 32 + mi * 16 + gid;
            int rl = wm * 32 + mi * 16 + gid;
            #pragma unroll
            for (int q = 0; q < 2; ++q) {
                int cl = wn * 16 + q * 8 + tig * 2;
                int c  = nc * NC + cl;
                float2 b0 = *(const float2*)(bias + (size_t)r0 * SEQ + c);
                float e0 = __expf(acc[mi][q][0] + b0.x);
                float e1 = __expf(acc[mi][q][1] + b0.y);
                *(float2*)(outW + ((size_t)bh * SEQ + r0) * SEQ + c) = make_float2(e0, e1);
                rs[mi][0] += e0 + e1;
                float2 b1 = *(const float2*)(bias + (size_t)(r0 + 8) * SEQ + c);
                float e2 = __expf(acc[mi][q][2] + b1.x);
                float e3 = __expf(acc[mi][q][3] + b1.y);
                *(float2*)(outW + ((size_t)bh * SEQ + r0 + 8) * SEQ + c) = make_float2(e2, e3);
                rs[mi][1] += e2 + e3;

                __nv_bfloat16 h0 = __float2bfloat16(e0), h1 = __float2bfloat16(e1);
                __nv_bfloat16 l0 = __float2bfloat16(e0 - __bfloat162float(h0));
                __nv_bfloat16 l1 = __float2bfloat16(e1 - __bfloat162float(h1));
                *(uint32_t*)(sm + P_W + rl * S1 + cl * 2) = pack2(h0, h1);
                *(uint32_t*)(sm + P_W + 18432 + rl * S1 + cl * 2) = pack2(l0, l1);
                __nv_bfloat16 h2 = __float2bfloat16(e2), h3 = __float2bfloat16(e3);
                __nv_bfloat16 l2 = __float2bfloat16(e2 - __bfloat162float(h2));
                __nv_bfloat16 l3 = __float2bfloat16(e3 - __bfloat162float(h3));
                *(uint32_t*)(sm + P_W + (rl + 8) * S1 + cl * 2) = pack2(h2, h3);
                *(uint32_t*)(sm + P_W + 18432 + (rl + 8) * S1 + cl * 2) = pack2(l2, l3);
            }
        }
        __syncthreads();   // W tile visible; QK done with K buf

        // ---- PV MMA: accO += E @ V (V buf nc&1) ----
        const uint32_t vbuf = sb + P_V + (uint32_t)(nc & 1) * 18432;
        #pragma unroll
        for (int kt = 0; kt < 4; ++kt) {
            uint32_t wh_[2][4], wl_[2][4];
            #pragma unroll
            for (int mi = 0; mi < 2; ++mi) {
                uint32_t ra = sb + P_W + (uint32_t)((wm * 32 + mi * 16 + (lane & 15)) * S1
                             + (lane >> 4) * 16 + kt * 32);
                LDSM4(wh_[mi], ra);
                LDSM4(wl_[mi], ra + 18432);
            }
            uint32_t vh4[4], vl4[4];
            uint32_t addr = vbuf + (uint32_t)((wn * 16 + (lane & 15)) * S1
                           + (lane >> 4) * 16 + kt * 32);
            LDSM4(vh4, addr);
            LDSM4(vl4, addr + 9216);
            #pragma unroll
            for (int q = 0; q < 2; ++q)
                #pragma unroll
                for (int mi = 0; mi < 2; ++mi) {
                    float* c = accO[mi][q];
                    mma_bf16(c, wh_[mi], vh4[q], vh4[q + 2]);
                    mma_bf16(c, wh_[mi], vl4[q], vl4[q + 2]);
                    mma_bf16(c, wl_[mi], vh4[q], vh4[q + 2]);
                }
        }

        // ---- split-STS next K/V into other buffer ----
        if (nc < 15) {
            char* kh = sm + P_K + ((nc + 1) & 1) * 18432;
            #pragma unroll
            for (int j = 0; j < 2; ++j) {
                uint2 h, l; split4(*(float4*)(kraw + j * 4), h, l);
                *(uint2*)(kh + rK * S1 + (cK + j * 4) * 2) = h;
                *(uint2*)(kh + 9216 + rK * S1 + (cK + j * 4) * 2) = l;
            }
            char* vh = sm + P_V + ((nc + 1) & 1) * 18432;
            #pragma unroll
            for (int d = 0; d < 4; ++d) {
                __nv_bfloat16 ha = __float2bfloat16(fa[d]);
                __nv_bfloat16 hb = __float2bfloat16(fb[d]);
                __nv_bfloat16 la = __float2bfloat16(fa[d] - __bfloat162float(ha));
                __nv_bfloat16 lb = __float2bfloat16(fb[d] - __bfloat162float(hb));
                *(uint32_t*)(vh + (d0 + d) * S1 + s0 * 2) = pack2(ha, hb);
                *(uint32_t*)(vh + 9216 + (d0 + d) * S1 + s0 * 2) = pack2(la, lb);
            }
        }
    }

    // ---- reduce row sums -> 1/sum ----
    {
        float* st = (float*)(sm + ST_SUM);
        int slot = wn * 4 + tig;
        #pragma unroll
        for (int mi = 0; mi < 2; ++mi)
            #pragma unroll
            for (int h = 0; h < 2; ++h)
                st[(wm * 32 + mi * 16 + h * 8 + gid) * 16 + slot] = rs[mi][h];
    }
    __syncthreads();
    if (tid < 128) {
        float* st = (float*)(sm + ST_SUM);
        float s = 0.f;
        #pragma unroll
        for (int i = 0; i < 16; ++i) s += st[tid * 16 + i];
        float iv = 1.f / s;
        ((float*)(sm + ST_INV))[tid] = iv;
        g_inv[(size_t)bh * SEQ + qb + tid] = iv;
    }
    __syncthreads();

    // ---- O epilogue: scale by inv, store ----
    #pragma unroll
    for (int mi = 0; mi < 2; ++mi) {
        int rl = wm * 32 + mi * 16 + gid;
        int r0 = qb + rl;
        float i0 = ((const float*)(sm + ST_INV))[rl];
        float i1 = ((const float*)(sm + ST_INV))[rl + 8];
        #pragma unroll
        for (int q = 0; q < 2; ++q) {
            int c = wn * 16 + q * 8 + tig * 2;
            *(float2*)(outO + ((size_t)bh * SEQ + r0) * DH + c) =
                make_float2(accO[mi][q][0] * i0, accO[mi][q][1] * i0);
            *(float2*)(outO + ((size_t)bh * SEQ + r0 + 8) * DH + c) =
                make_float2(accO[mi][q][2] * i1, accO[mi][q][3] * i1);
        }
    }
}

// ---- kernel 2: W = E * inv[row], in place, streaming ----
__global__ __launch_bounds__(256, 8)
void norm_w(float* __restrict__ outW)
{
    int row = blockIdx.x * 8 + (threadIdx.x >> 5);
    int lane = threadIdx.x & 31;
    float inv = g_inv[row];
    float4* p = (float4*)(outW + (size_t)row * SEQ);
    #pragma unroll
    for (int j = 0; j < 8; ++j) {
        float4 v = p[lane + j * 32];
        v.x *= inv; v.y *= inv; v.z *= inv; v.w *= inv;
        p[lane + j * 32] = v;
    }
}

extern "C" void kernel_launch(void* const* d_in, const int* in_sizes, int n_in,
                              void* d_out, int out_size) {
    const float* Q    = (const float*)d_in[0];
    const float* K    = (const float*)d_in[1];
    const float* V    = (const float*)d_in[2];
    const float* bias = (const float*)d_in[3];
    float* outO = (float*)d_out;
    float* outW = outO + (size_t)NBH * SEQ * DH;

    static int inited = 0;
    if (!inited) {
        cudaFuncSetAttribute(attn_k1, cudaFuncAttributeMaxDynamicSharedMemorySize, SMEM_TOTAL);
        inited = 1;
    }
    dim3 grid(SEQ / MT, NBH);
    attn_k1<<<grid, 512, SMEM_TOTAL>>>(Q, K, V, bias, outO, outW);
    norm_w<<<(NBH * SEQ) / 8, 256>>>(outW);
}